// round 5
// baseline (speedup 1.0000x reference)
#include <cuda_runtime.h>
#include <cuda_bf16.h>
#include <cuda_fp16.h>
#include <cstdint>

#define NROWS  131072
#define DDIM   64
#define KCODES 1024
#define BM2    256
#define BKC    512            // codes per B chunk
#define NCHK   (KCODES / BKC)
#define MARGIN 2e-3f

// ---------------- device scratch ----------------
__device__ float g_cnorm[KCODES];
__device__ float g_counts[KCODES];
__device__ float g_isum[DDIM * KCODES];
__device__ int   g_idx[NROWS];
__device__ float g_csize[KCODES];
__device__ float g_cbT[KCODES * DDIM];
__device__ __align__(16) __half g_cbh[KCODES * DDIM];  // [code][dim] fp16 of -2c (hi)
__device__ __align__(16) __half g_cbl[KCODES * DDIM];  // residual (lo)
__device__ int   g_nflag;
__device__ int   g_flag[NROWS];

__device__ __forceinline__ uint32_t smem_u32(const void* p) {
    uint32_t a;
    asm("{ .reg .u64 t; cvta.to.shared.u64 t, %1; cvt.u32.u64 %0, t; }" : "=r"(a) : "l"(p));
    return a;
}

// ---------------- kernel 0a: zero scratch ----------------
__global__ void k_zero(float* __restrict__ loss_slot) {
    int t = blockIdx.x * blockDim.x + threadIdx.x;   // 65536
    g_isum[t] = 0.0f;
    if (t < KCODES) g_counts[t] = 0.0f;
    if (t == 0) { *loss_slot = 0.0f; g_nflag = 0; }
}

// ---------------- kernel 0b: codebook -> fp16 split of (-2c) + norms ----------------
__global__ void k_split(const float* __restrict__ cb) {
    int k = blockIdx.x * blockDim.x + threadIdx.x;   // 1024 threads
    float s = 0.0f;
#pragma unroll
    for (int d = 0; d < DDIM; d++) {
        float v = cb[d * KCODES + k];
        s = fmaf(v, v, s);
        float t = -2.0f * v;
        __half h = __float2half_rn(t);
        __half l = __float2half_rn(t - __half2float(h));
        g_cbh[k * DDIM + d] = h;
        g_cbl[k * DDIM + d] = l;
    }
    g_cnorm[k] = s;
}

// ---------------- kernel 1: split-fp16 mma distances + argmin + flags ----------
// 512 threads, 16 warps; warp w owns rows [w*16, w*16+16).
// smem bytes: Ah 36864 | Al 36864 | Bh 73728 | Bl 73728 | cn 4096 = 225280
#define SM_AH 0
#define SM_AL 36864
#define SM_BH 73728
#define SM_BL 147456
#define SM_CN 221184
#define SM_MAIN_TOT 225280

#define MERGE(b, s, i, m) do {                                     \
    float ob = __shfl_xor_sync(0xffffffffu, (b), (m));             \
    float os = __shfl_xor_sync(0xffffffffu, (s), (m));             \
    int   oi = __shfl_xor_sync(0xffffffffu, (i), (m));             \
    float ns = fminf(fminf((s), os), fmaxf((b), ob));              \
    if (ob < (b) || (ob == (b) && oi < (i))) { (b) = ob; (i) = oi; } \
    (s) = ns;                                                      \
} while (0)

// resolve one row's chunk-pending (m1,m2,pid) into global (g1,g2,gc).
// All 4 quad lanes execute identically (values are quad-uniform post-MERGE).
__device__ __forceinline__ void resolve_pair(
    int lane, int chunk, int arow,
    const char* smem, const float* s_cn,
    float m1, float m2, int pid,
    float& g1, float& g2, int& gc)
{
    int c0 = pid * 2;
    int lb = c0 - chunk * BKC;          // local B row
    int q  = lane & 3;
    const __half2* ah = (const __half2*)(smem + SM_AH + arow * 144 + q * 32);
    const __half2* al = (const __half2*)(smem + SM_AL + arow * 144 + q * 32);
    const __half2* b0h = (const __half2*)(smem + SM_BH + lb * 144 + q * 32);
    const __half2* b0l = (const __half2*)(smem + SM_BL + lb * 144 + q * 32);
    const __half2* b1h = (const __half2*)(smem + SM_BH + (lb + 1) * 144 + q * 32);
    const __half2* b1l = (const __half2*)(smem + SM_BL + (lb + 1) * 144 + q * 32);
    float s0 = 0.f, s1 = 0.f;
#pragma unroll
    for (int i = 0; i < 8; i++) {
        float2 a  = __half22float2(ah[i]);
        float2 aL = __half22float2(al[i]);
        float2 p0 = __half22float2(b0h[i]);
        float2 p0L= __half22float2(b0l[i]);
        float2 p1 = __half22float2(b1h[i]);
        float2 p1L= __half22float2(b1l[i]);
        float ax = a.x + aL.x, ay = a.y + aL.y;
        s0 = fmaf(ax, p0.x + p0L.x, s0);
        s0 = fmaf(ay, p0.y + p0L.y, s0);
        s1 = fmaf(ax, p1.x + p1L.x, s1);
        s1 = fmaf(ay, p1.y + p1L.y, s1);
    }
    s0 += __shfl_xor_sync(0xffffffffu, s0, 1);
    s0 += __shfl_xor_sync(0xffffffffu, s0, 2);
    s1 += __shfl_xor_sync(0xffffffffu, s1, 1);
    s1 += __shfl_xor_sync(0xffffffffu, s1, 2);
    float d0 = s0 + s_cn[c0];
    float d1 = s1 + s_cn[c0 + 1];
    float bmin = fminf(d0, d1);
    int   bc   = (d1 < d0) ? c0 + 1 : c0;
    float oth  = fmaxf(d0, d1);
    float cand2 = fminf(oth, m2);
    if (bmin < g1) { g2 = fminf(g1, cand2); g1 = bmin; gc = bc; }
    else           { g2 = fminf(g2, fminf(bmin, m2)); }
    (void)m1;
}

extern __shared__ char smemc[];
__global__ void __launch_bounds__(512, 1)
k_main(const float* __restrict__ x) {
    char* Ah = smemc + SM_AH;
    char* Al = smemc + SM_AL;
    char* Bh = smemc + SM_BH;
    char* Bl = smemc + SM_BL;
    float* s_cn = (float*)(smemc + SM_CN);

    const int tid  = threadIdx.x;
    const int lane = tid & 31;
    const int wid  = tid >> 5;
    const int rowbase = blockIdx.x * BM2;

#pragma unroll
    for (int i = 0; i < 2; i++) s_cn[tid + i * 512] = g_cnorm[tid + i * 512];

    // load + split A tile (256 rows x 64 dims): 4096 float4
    {
        const float4* xg = (const float4*)(x + (size_t)rowbase * DDIM);
#pragma unroll
        for (int i = 0; i < 8; i++) {
            int v = tid + i * 512;
            int r = v >> 4, d4 = (v & 15) << 2;
            float4 f = xg[v];
            float vv[4] = {f.x, f.y, f.z, f.w};
            ushort hh[4], ll[4];
#pragma unroll
            for (int q = 0; q < 4; q++) {
                __half h = __float2half_rn(vv[q]);
                __half l = __float2half_rn(vv[q] - __half2float(h));
                hh[q] = __half_as_ushort(h);
                ll[q] = __half_as_ushort(l);
            }
            uint32_t off = (uint32_t)r * 144 + (uint32_t)d4 * 2;
            *(uint2*)(Ah + off) = make_uint2((uint32_t)hh[1] << 16 | hh[0],
                                             (uint32_t)hh[3] << 16 | hh[2]);
            *(uint2*)(Al + off) = make_uint2((uint32_t)ll[1] << 16 | ll[0],
                                             (uint32_t)ll[3] << 16 | ll[2]);
        }
    }
    __syncthreads();

    const uint32_t AhB = smem_u32(Ah);
    const uint32_t AlB = smem_u32(Al);
    const uint32_t BhB = smem_u32(Bh);
    const uint32_t BlB = smem_u32(Bl);
    const int m0 = wid * 16;

    // A fragments (kept in regs): 4 k-tiles x x4 for hi and lo
    uint32_t a_h[4][4], a_l[4][4];
    {
        uint32_t arh = AhB + (uint32_t)(m0 + (lane & 15)) * 144 + (uint32_t)(lane >> 4) * 16;
        uint32_t arl = AlB + (uint32_t)(m0 + (lane & 15)) * 144 + (uint32_t)(lane >> 4) * 16;
#pragma unroll
        for (int kt = 0; kt < 4; kt++) {
            asm volatile("ldmatrix.sync.aligned.m8n8.x4.shared.b16 {%0,%1,%2,%3}, [%4];"
                : "=r"(a_h[kt][0]), "=r"(a_h[kt][1]), "=r"(a_h[kt][2]), "=r"(a_h[kt][3])
                : "r"(arh + kt * 32));
            asm volatile("ldmatrix.sync.aligned.m8n8.x4.shared.b16 {%0,%1,%2,%3}, [%4];"
                : "=r"(a_l[kt][0]), "=r"(a_l[kt][1]), "=r"(a_l[kt][2]), "=r"(a_l[kt][3])
                : "r"(arl + kt * 32));
        }
    }

    float g1l = 3.4e38f, g2l = 3.4e38f, g1h = 3.4e38f, g2h = 3.4e38f;
    int   gcl = 0, gch = 0;
    const uint32_t bidx0 = (uint32_t)(lane & 7) * 144 + (uint32_t)(lane >> 3) * 16;
    const int arow_lo = m0 + (lane >> 2);
    const int arow_hi = arow_lo + 8;

    for (int chunk = 0; chunk < NCHK; chunk++) {
        __syncthreads();   // prior chunk recovery done before B overwrite
        // load B chunk (512 codes x 64 dims, hi+lo): 4096 uint4 each
        {
            const uint4* gh = (const uint4*)g_cbh;
            const uint4* gl = (const uint4*)g_cbl;
#pragma unroll
            for (int i = 0; i < 8; i++) {
                int v = tid + i * 512;
                int lc = v >> 3, d8 = v & 7;
                uint32_t o = (uint32_t)lc * 144 + (uint32_t)d8 * 16;
                int gi = (chunk * BKC + lc) * 8 + d8;
                *(uint4*)(Bh + o) = gh[gi];
                *(uint4*)(Bl + o) = gl[gi];
            }
        }
        __syncthreads();

        float m1l = 3.4e38f, m2l = 3.4e38f, m1h = 3.4e38f, m2h = 3.4e38f;
        int   pidl = 0, pidh = 0;
        const int pidbase = chunk * (BKC / 2) + (lane & 3);

#pragma unroll 2
        for (int nt = 0; nt < BKC / 8; nt++) {
            uint32_t ad = bidx0 + (uint32_t)nt * (8 * 144);
            uint32_t bh0, bh1, bh2, bh3, bh4, bh5, bh6, bh7;
            uint32_t bl0, bl1, bl2, bl3, bl4, bl5, bl6, bl7;
            asm volatile("ldmatrix.sync.aligned.m8n8.x4.shared.b16 {%0,%1,%2,%3}, [%4];"
                : "=r"(bh0), "=r"(bh1), "=r"(bh2), "=r"(bh3) : "r"(BhB + ad));
            asm volatile("ldmatrix.sync.aligned.m8n8.x4.shared.b16 {%0,%1,%2,%3}, [%4];"
                : "=r"(bh4), "=r"(bh5), "=r"(bh6), "=r"(bh7) : "r"(BhB + ad + 64));
            asm volatile("ldmatrix.sync.aligned.m8n8.x4.shared.b16 {%0,%1,%2,%3}, [%4];"
                : "=r"(bl0), "=r"(bl1), "=r"(bl2), "=r"(bl3) : "r"(BlB + ad));
            asm volatile("ldmatrix.sync.aligned.m8n8.x4.shared.b16 {%0,%1,%2,%3}, [%4];"
                : "=r"(bl4), "=r"(bl5), "=r"(bl6), "=r"(bl7) : "r"(BlB + ad + 64));

            // two independent accumulator chains to shorten RAW depth
            float cA0 = 0.f, cA1 = 0.f, cA2 = 0.f, cA3 = 0.f;
            float cB0 = 0.f, cB1 = 0.f, cB2 = 0.f, cB3 = 0.f;
#define MMA(c0_, c1_, c2_, c3_, A_, B0_, B1_)                                          \
            asm volatile("mma.sync.aligned.m16n8k16.row.col.f32.f16.f16.f32 "          \
                "{%0,%1,%2,%3}, {%4,%5,%6,%7}, {%8,%9}, {%0,%1,%2,%3};"                \
                : "+f"(c0_), "+f"(c1_), "+f"(c2_), "+f"(c3_)                           \
                : "r"((A_)[0]), "r"((A_)[1]), "r"((A_)[2]), "r"((A_)[3]),              \
                  "r"(B0_), "r"(B1_))
            MMA(cA0, cA1, cA2, cA3, a_h[0], bh0, bh1);
            MMA(cB0, cB1, cB2, cB3, a_l[0], bh0, bh1);
            MMA(cA0, cA1, cA2, cA3, a_h[1], bh2, bh3);
            MMA(cB0, cB1, cB2, cB3, a_l[1], bh2, bh3);
            MMA(cA0, cA1, cA2, cA3, a_h[2], bh4, bh5);
            MMA(cB0, cB1, cB2, cB3, a_l[2], bh4, bh5);
            MMA(cA0, cA1, cA2, cA3, a_h[3], bh6, bh7);
            MMA(cB0, cB1, cB2, cB3, a_l[3], bh6, bh7);
            MMA(cA0, cA1, cA2, cA3, a_h[0], bl0, bl1);
            MMA(cA0, cA1, cA2, cA3, a_h[1], bl2, bl3);
            MMA(cA0, cA1, cA2, cA3, a_h[2], bl4, bl5);
            MMA(cA0, cA1, cA2, cA3, a_h[3], bl6, bl7);
#undef MMA
            int code0 = chunk * BKC + nt * 8 + ((lane & 3) << 1);
            float2 cn = *(const float2*)(s_cn + code0);
            float d0 = (cA0 + cB0) + cn.x;
            float d1 = (cA1 + cB1) + cn.y;
            float d2 = (cA2 + cB2) + cn.x;
            float d3 = (cA3 + cB3) + cn.y;
            float ml = fminf(d0, d1);
            float mh = fminf(d2, d3);
            int pid = pidbase + nt * 4;
            if (ml < m1l) { m2l = m1l; m1l = ml; pidl = pid; } else if (ml < m2l) m2l = ml;
            if (mh < m1h) { m2h = m1h; m1h = mh; pidh = pid; } else if (mh < m2h) m2h = mh;
        }

        // quad merge of chunk pendings (leaves consensus in all 4 lanes)
        MERGE(m1l, m2l, pidl, 1); MERGE(m1l, m2l, pidl, 2);
        MERGE(m1h, m2h, pidh, 1); MERGE(m1h, m2h, pidh, 2);

        // resolve the winning pair for each row from smem (quad-cooperative)
        resolve_pair(lane, chunk, arow_lo, smemc, s_cn, m1l, m2l, pidl, g1l, g2l, gcl);
        resolve_pair(lane, chunk, arow_hi, smemc, s_cn, m1h, m2h, pidh, g1h, g2h, gch);
    }

    if ((lane & 3) == 0) {
        int g = lane >> 2;
        int row_lo = rowbase + m0 + g;
        int row_hi = row_lo + 8;
        g_idx[row_lo] = gcl;
        g_idx[row_hi] = gch;
        if (g2l - g1l < MARGIN) { int p = atomicAdd(&g_nflag, 1); g_flag[p] = row_lo; }
        if (g2h - g1h < MARGIN) { int p = atomicAdd(&g_nflag, 1); g_flag[p] = row_hi; }
    }
}

// ---------------- kernel 1b: exact fp32 re-solve, one warp per flagged row ------
__global__ void __launch_bounds__(256, 4)
k_fallback(const float* __restrict__ x, const float* __restrict__ cb) {
    __shared__ float xs[8][64];
    const int lane = threadIdx.x & 31;
    const int w    = threadIdx.x >> 5;
    const int count = g_nflag;

    for (int fi = blockIdx.x * 8 + w; fi < count; fi += gridDim.x * 8) {
        int row = g_flag[fi];
        xs[w][lane]      = x[(size_t)row * DDIM + lane];
        xs[w][lane + 32] = x[(size_t)row * DDIM + lane + 32];
        __syncwarp();

        float best = 3.4e38f;
        int   bidx = 0;
#pragma unroll
        for (int tg = 0; tg < 8; tg++) {
            int k0 = tg * 128 + lane * 4;
            float a0 = 0.f, a1 = 0.f, a2 = 0.f, a3 = 0.f;
#pragma unroll 16
            for (int d = 0; d < DDIM; d++) {
                float xv = xs[w][d];
                float4 c4 = *(const float4*)(cb + d * KCODES + k0);
                a0 = fmaf(xv, c4.x, a0);
                a1 = fmaf(xv, c4.y, a1);
                a2 = fmaf(xv, c4.z, a2);
                a3 = fmaf(xv, c4.w, a3);
            }
            float4 cn = *(const float4*)(g_cnorm + k0);
            float d0 = fmaf(-2.f, a0, cn.x);
            float d1 = fmaf(-2.f, a1, cn.y);
            float d2 = fmaf(-2.f, a2, cn.z);
            float d3 = fmaf(-2.f, a3, cn.w);
            if (d0 < best) { best = d0; bidx = k0;     }
            if (d1 < best) { best = d1; bidx = k0 + 1; }
            if (d2 < best) { best = d2; bidx = k0 + 2; }
            if (d3 < best) { best = d3; bidx = k0 + 3; }
        }
#pragma unroll
        for (int m = 1; m < 32; m <<= 1) {
            float ob = __shfl_xor_sync(0xffffffffu, best, m);
            int   oi = __shfl_xor_sync(0xffffffffu, bidx, m);
            if (ob < best || (ob == best && oi < bidx)) { best = ob; bidx = oi; }
        }
        if (lane == 0) g_idx[row] = bidx;
        __syncwarp();
    }
}

// ---------------- kernel 1c: scatter EMA statistics ----------------
__global__ void k_scatter(const float* __restrict__ x) {
    int t = blockIdx.x * 256 + threadIdx.x;   // 2048 blocks x 256 = 4*NROWS
    int row = t >> 2, q = t & 3;
    int code = g_idx[row];
    if (q == 0) atomicAdd(&g_counts[code], 1.0f);
    const float4* xr = (const float4*)(x + (size_t)row * DDIM + q * 16);
#pragma unroll
    for (int j = 0; j < 4; j++) {
        float4 f = xr[j];
        int d = q * 16 + j * 4;
        atomicAdd(&g_isum[(d + 0) * KCODES + code], f.x);
        atomicAdd(&g_isum[(d + 1) * KCODES + code], f.y);
        atomicAdd(&g_isum[(d + 2) * KCODES + code], f.z);
        atomicAdd(&g_isum[(d + 3) * KCODES + code], f.w);
    }
}

// ---------------- kernel 2a: EMA cluster sizes ----------------
__global__ void k_stats(const float* __restrict__ ema_cs, float* __restrict__ out_cs) {
    int k = threadIdx.x;
    float cs = fmaf(0.99f, ema_cs[k], 0.01f * g_counts[k]);
    out_cs[k] = cs;
    __shared__ float red[32];
    __shared__ float s_n;
    float s = cs;
#pragma unroll
    for (int m = 16; m >= 1; m >>= 1) s += __shfl_xor_sync(0xffffffffu, s, m);
    int lane = k & 31, warp = k >> 5;
    if (lane == 0) red[warp] = s;
    __syncthreads();
    if (warp == 0) {
        float v = red[lane];
#pragma unroll
        for (int m = 16; m >= 1; m >>= 1) v += __shfl_xor_sync(0xffffffffu, v, m);
        if (lane == 0) s_n = v;
    }
    __syncthreads();
    float n = s_n;
    g_csize[k] = ((cs + 1e-5f) / (n + KCODES * 1e-5f)) * n;
}

// ---------------- kernel 2b: new ema_sum + codebook ----------------
__global__ void k_upd(const float* __restrict__ ema_sum,
                      float* __restrict__ out_sum, float* __restrict__ out_cb) {
    int e = blockIdx.x * blockDim.x + threadIdx.x;
    int d = e >> 10, k = e & 1023;
    float num = fmaf(0.99f, ema_sum[e], 0.01f * g_isum[e]);
    out_sum[e] = num;
    float ncb = num / g_csize[k];
    out_cb[e] = ncb;
    g_cbT[k * DDIM + d] = ncb;
}

// ---------------- kernel 3: quantize + loss ----------------
__global__ void k_quant(const float* __restrict__ x,
                        float* __restrict__ out_q, float* __restrict__ out_loss) {
    int t = blockIdx.x * 256 + threadIdx.x;
    float lsum = 0.0f;
#pragma unroll
    for (int it = 0; it < 2; it++) {
        int e4 = t + it * (4096 * 256);
        int r = e4 >> 4, d4 = (e4 & 15) << 2;
        int code = g_idx[r];
        float4 q4 = *(const float4*)(g_cbT + code * DDIM + d4);
        float4 x4 = *(const float4*)(x + ((size_t)e4 << 2));
        float dx0 = q4.x - x4.x, dx1 = q4.y - x4.y, dx2 = q4.z - x4.z, dx3 = q4.w - x4.w;
        float4 o;
        o.x = x4.x + dx0; o.y = x4.y + dx1; o.z = x4.z + dx2; o.w = x4.w + dx3;
        *(float4*)(out_q + ((size_t)e4 << 2)) = o;
        lsum = fmaf(dx0, dx0, lsum); lsum = fmaf(dx1, dx1, lsum);
        lsum = fmaf(dx2, dx2, lsum); lsum = fmaf(dx3, dx3, lsum);
    }
    __shared__ float red[8];
#pragma unroll
    for (int m = 16; m >= 1; m >>= 1) lsum += __shfl_xor_sync(0xffffffffu, lsum, m);
    int lane = threadIdx.x & 31, warp = threadIdx.x >> 5;
    if (lane == 0) red[warp] = lsum;
    __syncthreads();
    if (warp == 0) {
        float v = (lane < 8) ? red[lane] : 0.0f;
#pragma unroll
        for (int m = 4; m >= 1; m >>= 1) v += __shfl_xor_sync(0xffffffffu, v, m);
        if (lane == 0) atomicAdd(out_loss, v * (1.0f / 8388608.0f));
    }
}

// ---------------- launch ----------------
extern "C" void kernel_launch(void* const* d_in, const int* in_sizes, int n_in,
                              void* d_out, int out_size) {
    const float* x       = (const float*)d_in[0];
    const float* cb      = (const float*)d_in[1];
    const float* ema_cs  = (const float*)d_in[2];
    const float* ema_sum = (const float*)d_in[3];

    float* out      = (float*)d_out;
    float* out_q    = out;
    float* out_loss = out + 8388608;
    float* out_cb   = out_loss + 1;
    float* out_cs   = out_cb + 65536;
    float* out_sum  = out_cs + 1024;

    static bool attr_set = false;
    if (!attr_set) {
        cudaFuncSetAttribute(k_main, cudaFuncAttributeMaxDynamicSharedMemorySize, SM_MAIN_TOT);
        attr_set = true;
    }

    k_zero<<<64, 1024>>>(out_loss);
    k_split<<<4, 256>>>(cb);
    k_main<<<NROWS / BM2, 512, SM_MAIN_TOT>>>(x);
    k_fallback<<<148, 256>>>(x, cb);
    k_scatter<<<2048, 256>>>(x);
    k_stats<<<1, 1024>>>(ema_cs, out_cs);
    k_upd<<<64, 1024>>>(ema_sum, out_sum, out_cb);
    k_quant<<<4096, 256>>>(x, out_q, out_loss);
}

// round 6
// speedup vs baseline: 1.3227x; 1.3227x over previous
#include <cuda_runtime.h>
#include <cuda_bf16.h>
#include <cuda_fp16.h>
#include <cstdint>

#define NROWS  131072
#define DDIM   64
#define KCODES 1024
#define BM2    256          // rows per block in k_main
#define MARGIN 0.15f
#define FB_PITCH 132

// ---------------- device scratch ----------------
__device__ float g_cnorm[KCODES];
__device__ float g_counts[KCODES];
__device__ float g_isum[DDIM * KCODES];
__device__ int   g_idx[NROWS];
__device__ float g_csize[KCODES];
__device__ float g_cbT[KCODES * DDIM];
__device__ __align__(16) __half g_cbh[KCODES * DDIM];  // [code][dim] fp16 codebook
__device__ int   g_nflag;
__device__ int   g_flag[NROWS];

__device__ __forceinline__ uint32_t smem_u32(const void* p) {
    uint32_t a;
    asm("{ .reg .u64 t; cvta.to.shared.u64 t, %1; cvt.u32.u64 %0, t; }" : "=r"(a) : "l"(p));
    return a;
}

// ---------------- kernel 0a: zero scratch ----------------
__global__ void k_zero(float* __restrict__ loss_slot) {
    int t = blockIdx.x * blockDim.x + threadIdx.x;   // 65536
    g_isum[t] = 0.0f;
    if (t < KCODES) g_counts[t] = 0.0f;
    if (t == 0) { *loss_slot = 0.0f; g_nflag = 0; }
}

// ---------------- kernel 0b: codebook -> fp16 [code][dim] + norms ----------------
__global__ void k_split(const float* __restrict__ cb) {
    int k = blockIdx.x * blockDim.x + threadIdx.x;   // 1024 threads
    float s = 0.0f;
#pragma unroll
    for (int d = 0; d < DDIM; d++) {
        float v = cb[d * KCODES + k];
        s = fmaf(v, v, s);
        g_cbh[k * DDIM + d] = __float2half_rn(v);
    }
    g_cnorm[k] = s;
}

// ---------------- kernel 1: fp16 mma.sync approx distances + argmin + flags ----------
// 512 threads, 16 warps; warp w owns rows [w*16, w*16+16) x all 1024 codes.
// smem: A fp16 [256][72] (36864 B) | B fp16 [1024][72] (147456 B) | cn [1024] f32 (4096 B)
#define SMA_BYTES 36864
#define SMB_BYTES 147456
#define SM_MAIN_TOT (SMA_BYTES + SMB_BYTES + 4096)

#define MERGE(b, s, i, m) do {                                     \
    float ob = __shfl_xor_sync(0xffffffffu, (b), (m));             \
    float os = __shfl_xor_sync(0xffffffffu, (s), (m));             \
    int   oi = __shfl_xor_sync(0xffffffffu, (i), (m));             \
    float ns = fminf(fminf((s), os), fmaxf((b), ob));              \
    if (ob < (b) || (ob == (b) && oi < (i))) { (b) = ob; (i) = oi; } \
    (s) = ns;                                                      \
} while (0)

extern __shared__ char smemc[];
__global__ void __launch_bounds__(512, 1)
k_main(const float* __restrict__ x) {
    char* Abf = smemc;                       // row stride 144 B (72 fp16)
    char* Bbf = smemc + SMA_BYTES;           // row stride 144 B
    float* s_cn = (float*)(smemc + SMA_BYTES + SMB_BYTES);

    const int tid  = threadIdx.x;
    const int lane = tid & 31;
    const int wid  = tid >> 5;
    const int rowbase = blockIdx.x * BM2;

    // load fp16 codebook into smem: 8192 uint4
    {
        const uint4* gB = (const uint4*)g_cbh;
#pragma unroll
        for (int i = 0; i < 16; i++) {
            int v = tid + i * 512;
            int rc = v >> 3, d8 = v & 7;
            *(uint4*)(Bbf + rc * 144 + d8 * 16) = gB[v];
        }
    }
#pragma unroll
    for (int i = 0; i < 2; i++) s_cn[tid + i * 512] = g_cnorm[tid + i * 512];

    // load + convert A tile (256 rows x 64 dims): 4096 float4
    {
        const float4* xg = (const float4*)(x + (size_t)rowbase * DDIM);
#pragma unroll
        for (int i = 0; i < 8; i++) {
            int v = tid + i * 512;
            int r = v >> 4, d4 = (v & 15) << 2;
            float4 f = xg[v];
            uint32_t lo = ((uint32_t)__half_as_ushort(__float2half_rn(f.y)) << 16)
                        |  (uint32_t)__half_as_ushort(__float2half_rn(f.x));
            uint32_t hi = ((uint32_t)__half_as_ushort(__float2half_rn(f.w)) << 16)
                        |  (uint32_t)__half_as_ushort(__float2half_rn(f.z));
            *(uint2*)(Abf + r * 144 + d4 * 2) = make_uint2(lo, hi);
        }
    }
    __syncthreads();

    const uint32_t Abase = smem_u32(Abf);
    const uint32_t Bbase = smem_u32(Bbf);
    const int m0 = wid * 16;

    // A fragments for m16 x k64: 4 k-tiles, ldmatrix x4 each (kept in regs)
    uint32_t a[4][4];
    {
        uint32_t ar = Abase + (uint32_t)(m0 + (lane & 15)) * 144 + (uint32_t)(lane >> 4) * 16;
#pragma unroll
        for (int kt = 0; kt < 4; kt++) {
            asm volatile("ldmatrix.sync.aligned.m8n8.x4.shared.b16 {%0,%1,%2,%3}, [%4];"
                : "=r"(a[kt][0]), "=r"(a[kt][1]), "=r"(a[kt][2]), "=r"(a[kt][3])
                : "r"(ar + kt * 32));
        }
    }

    float bl = 3.4e38f, sl = 3.4e38f, bh = 3.4e38f, sh = 3.4e38f;
    int   il = 0, ih = 0;
    const uint32_t baddr0 = Bbase + (uint32_t)(lane & 7) * 144 + (uint32_t)(lane >> 3) * 16;

#pragma unroll 4
    for (int nt = 0; nt < 128; nt++) {
        uint32_t b0, b1, b2, b3, b4, b5, b6, b7;
        uint32_t ad = baddr0 + (uint32_t)nt * (8 * 144);
        asm volatile("ldmatrix.sync.aligned.m8n8.x4.shared.b16 {%0,%1,%2,%3}, [%4];"
            : "=r"(b0), "=r"(b1), "=r"(b2), "=r"(b3) : "r"(ad));
        asm volatile("ldmatrix.sync.aligned.m8n8.x4.shared.b16 {%0,%1,%2,%3}, [%4];"
            : "=r"(b4), "=r"(b5), "=r"(b6), "=r"(b7) : "r"(ad + 64));

        float c0 = 0.f, c1 = 0.f, c2 = 0.f, c3 = 0.f;
        asm volatile("mma.sync.aligned.m16n8k16.row.col.f32.f16.f16.f32 "
            "{%0,%1,%2,%3}, {%4,%5,%6,%7}, {%8,%9}, {%0,%1,%2,%3};"
            : "+f"(c0), "+f"(c1), "+f"(c2), "+f"(c3)
            : "r"(a[0][0]), "r"(a[0][1]), "r"(a[0][2]), "r"(a[0][3]), "r"(b0), "r"(b1));
        asm volatile("mma.sync.aligned.m16n8k16.row.col.f32.f16.f16.f32 "
            "{%0,%1,%2,%3}, {%4,%5,%6,%7}, {%8,%9}, {%0,%1,%2,%3};"
            : "+f"(c0), "+f"(c1), "+f"(c2), "+f"(c3)
            : "r"(a[1][0]), "r"(a[1][1]), "r"(a[1][2]), "r"(a[1][3]), "r"(b2), "r"(b3));
        asm volatile("mma.sync.aligned.m16n8k16.row.col.f32.f16.f16.f32 "
            "{%0,%1,%2,%3}, {%4,%5,%6,%7}, {%8,%9}, {%0,%1,%2,%3};"
            : "+f"(c0), "+f"(c1), "+f"(c2), "+f"(c3)
            : "r"(a[2][0]), "r"(a[2][1]), "r"(a[2][2]), "r"(a[2][3]), "r"(b4), "r"(b5));
        asm volatile("mma.sync.aligned.m16n8k16.row.col.f32.f16.f16.f32 "
            "{%0,%1,%2,%3}, {%4,%5,%6,%7}, {%8,%9}, {%0,%1,%2,%3};"
            : "+f"(c0), "+f"(c1), "+f"(c2), "+f"(c3)
            : "r"(a[3][0]), "r"(a[3][1]), "r"(a[3][2]), "r"(a[3][3]), "r"(b6), "r"(b7));

        int code0 = nt * 8 + ((lane & 3) << 1);
        float cn0 = s_cn[code0], cn1 = s_cn[code0 + 1];
        float d0 = fmaf(-2.0f, c0, cn0);
        float d1 = fmaf(-2.0f, c1, cn1);
        float d2 = fmaf(-2.0f, c2, cn0);
        float d3 = fmaf(-2.0f, c3, cn1);
        if (d0 < bl) { sl = bl; bl = d0; il = code0;     } else if (d0 < sl) sl = d0;
        if (d1 < bl) { sl = bl; bl = d1; il = code0 + 1; } else if (d1 < sl) sl = d1;
        if (d2 < bh) { sh = bh; bh = d2; ih = code0;     } else if (d2 < sh) sh = d2;
        if (d3 < bh) { sh = bh; bh = d3; ih = code0 + 1; } else if (d3 < sh) sh = d3;
    }

    // reduce across the 4 lanes of each quad (same rows, different cols)
    MERGE(bl, sl, il, 1); MERGE(bl, sl, il, 2);
    MERGE(bh, sh, ih, 1); MERGE(bh, sh, ih, 2);

    if ((lane & 3) == 0) {
        int g = lane >> 2;
        int row_lo = rowbase + m0 + g;
        int row_hi = row_lo + 8;
        g_idx[row_lo] = il;
        g_idx[row_hi] = ih;
        if (sl - bl < MARGIN) { int p = atomicAdd(&g_nflag, 1); g_flag[p] = row_lo; }
        if (sh - bh < MARGIN) { int p = atomicAdd(&g_nflag, 1); g_flag[p] = row_hi; }
    }
}

// ---------------- kernel 1b: exact fp32 re-solve, 128 gathered rows per tile ----
__global__ void __launch_bounds__(256, 1)
k_fallback(const float* __restrict__ x, const float* __restrict__ cb) {
    float* As = (float*)smemc;                   // [64][FB_PITCH] transposed gathered tile
    float* Bs = As + DDIM * FB_PITCH;            // [64][FB_PITCH]

    const int tid = threadIdx.x;
    const int tx = tid & 15;     // code group
    const int ty = tid >> 4;     // row group
    const int count = g_nflag;

    for (int base = blockIdx.x * 128; base < count; base += gridDim.x * 128) {
        __syncthreads();
        // gather + transpose up to 128 flagged rows
        for (int v = tid; v < 128 * DDIM / 4; v += 256) {
            int r = v >> 4, d4 = (v & 15) << 2;
            int fi = base + r; if (fi > count - 1) fi = count - 1;
            int fr = g_flag[fi];
            float4 t4 = *(const float4*)(x + (size_t)fr * DDIM + d4);
            As[(d4 + 0) * FB_PITCH + r] = t4.x;
            As[(d4 + 1) * FB_PITCH + r] = t4.y;
            As[(d4 + 2) * FB_PITCH + r] = t4.z;
            As[(d4 + 3) * FB_PITCH + r] = t4.w;
        }

        float best[8]; int bidx[8];
#pragma unroll
        for (int i = 0; i < 8; i++) { best[i] = 3.4e38f; bidx[i] = 0; }

        for (int kc = 0; kc < KCODES; kc += 128) {
            __syncthreads();
#pragma unroll
            for (int v = tid; v < DDIM * 128 / 4; v += 256) {
                int d = v >> 5, c4 = (v & 31) << 2;
                *(float4*)(Bs + d * FB_PITCH + c4) = *(const float4*)(cb + d * KCODES + kc + c4);
            }
            __syncthreads();

            float acc[8][8];
#pragma unroll
            for (int i = 0; i < 8; i++)
#pragma unroll
                for (int j = 0; j < 8; j++) acc[i][j] = 0.0f;

#pragma unroll 8
            for (int d = 0; d < DDIM; d++) {
                float av[8], bv[8];
                float4 a0 = *(const float4*)(As + d * FB_PITCH + ty * 8);
                float4 a1 = *(const float4*)(As + d * FB_PITCH + ty * 8 + 4);
                float4 q0 = *(const float4*)(Bs + d * FB_PITCH + tx * 8);
                float4 q1 = *(const float4*)(Bs + d * FB_PITCH + tx * 8 + 4);
                av[0]=a0.x; av[1]=a0.y; av[2]=a0.z; av[3]=a0.w;
                av[4]=a1.x; av[5]=a1.y; av[6]=a1.z; av[7]=a1.w;
                bv[0]=q0.x; bv[1]=q0.y; bv[2]=q0.z; bv[3]=q0.w;
                bv[4]=q1.x; bv[5]=q1.y; bv[6]=q1.z; bv[7]=q1.w;
#pragma unroll
                for (int i = 0; i < 8; i++)
#pragma unroll
                    for (int j = 0; j < 8; j++)
                        acc[i][j] = fmaf(av[i], bv[j], acc[i][j]);
            }

#pragma unroll
            for (int j = 0; j < 8; j++) {
                int kidx = kc + tx * 8 + j;
                float cn = __ldg(&g_cnorm[kidx]);
#pragma unroll
                for (int i = 0; i < 8; i++) {
                    float dist = fmaf(-2.0f, acc[i][j], cn);
                    if (dist < best[i]) { best[i] = dist; bidx[i] = kidx; }
                }
            }
        }

#pragma unroll
        for (int i = 0; i < 8; i++) {
#pragma unroll
            for (int m = 1; m < 16; m <<= 1) {
                float ob = __shfl_xor_sync(0xffffffffu, best[i], m);
                int   oi = __shfl_xor_sync(0xffffffffu, bidx[i], m);
                if (ob < best[i] || (ob == best[i] && oi < bidx[i])) {
                    best[i] = ob; bidx[i] = oi;
                }
            }
        }
        if (tx == 0) {
#pragma unroll
            for (int i = 0; i < 8; i++) {
                int r = ty * 8 + i;
                if (base + r < count) g_idx[g_flag[base + r]] = bidx[i];
            }
        }
        __syncthreads();
    }
}

// ---------------- kernel 1c: scatter EMA statistics ----------------
__global__ void k_scatter(const float* __restrict__ x) {
    int t = blockIdx.x * 256 + threadIdx.x;   // 2048 blocks x 256 = 4*NROWS
    int row = t >> 2, q = t & 3;
    int code = g_idx[row];
    if (q == 0) atomicAdd(&g_counts[code], 1.0f);
    const float4* xr = (const float4*)(x + (size_t)row * DDIM + q * 16);
#pragma unroll
    for (int j = 0; j < 4; j++) {
        float4 f = xr[j];
        int d = q * 16 + j * 4;
        atomicAdd(&g_isum[(d + 0) * KCODES + code], f.x);
        atomicAdd(&g_isum[(d + 1) * KCODES + code], f.y);
        atomicAdd(&g_isum[(d + 2) * KCODES + code], f.z);
        atomicAdd(&g_isum[(d + 3) * KCODES + code], f.w);
    }
}

// ---------------- kernel 2a: EMA cluster sizes ----------------
__global__ void k_stats(const float* __restrict__ ema_cs, float* __restrict__ out_cs) {
    int k = threadIdx.x;
    float cs = fmaf(0.99f, ema_cs[k], 0.01f * g_counts[k]);
    out_cs[k] = cs;
    __shared__ float red[32];
    __shared__ float s_n;
    float s = cs;
#pragma unroll
    for (int m = 16; m >= 1; m >>= 1) s += __shfl_xor_sync(0xffffffffu, s, m);
    int lane = k & 31, warp = k >> 5;
    if (lane == 0) red[warp] = s;
    __syncthreads();
    if (warp == 0) {
        float v = red[lane];
#pragma unroll
        for (int m = 16; m >= 1; m >>= 1) v += __shfl_xor_sync(0xffffffffu, v, m);
        if (lane == 0) s_n = v;
    }
    __syncthreads();
    float n = s_n;
    g_csize[k] = ((cs + 1e-5f) / (n + KCODES * 1e-5f)) * n;
}

// ---------------- kernel 2b: new ema_sum + codebook ----------------
__global__ void k_upd(const float* __restrict__ ema_sum,
                      float* __restrict__ out_sum, float* __restrict__ out_cb) {
    int e = blockIdx.x * blockDim.x + threadIdx.x;
    int d = e >> 10, k = e & 1023;
    float num = fmaf(0.99f, ema_sum[e], 0.01f * g_isum[e]);
    out_sum[e] = num;
    float ncb = num / g_csize[k];
    out_cb[e] = ncb;
    g_cbT[k * DDIM + d] = ncb;
}

// ---------------- kernel 3: quantize + loss ----------------
__global__ void k_quant(const float* __restrict__ x,
                        float* __restrict__ out_q, float* __restrict__ out_loss) {
    int t = blockIdx.x * 256 + threadIdx.x;
    float lsum = 0.0f;
#pragma unroll
    for (int it = 0; it < 2; it++) {
        int e4 = t + it * (4096 * 256);
        int r = e4 >> 4, d4 = (e4 & 15) << 2;
        int code = g_idx[r];
        float4 q4 = *(const float4*)(g_cbT + code * DDIM + d4);
        float4 x4 = *(const float4*)(x + ((size_t)e4 << 2));
        float dx0 = q4.x - x4.x, dx1 = q4.y - x4.y, dx2 = q4.z - x4.z, dx3 = q4.w - x4.w;
        float4 o;
        o.x = x4.x + dx0; o.y = x4.y + dx1; o.z = x4.z + dx2; o.w = x4.w + dx3;
        *(float4*)(out_q + ((size_t)e4 << 2)) = o;
        lsum = fmaf(dx0, dx0, lsum); lsum = fmaf(dx1, dx1, lsum);
        lsum = fmaf(dx2, dx2, lsum); lsum = fmaf(dx3, dx3, lsum);
    }
    __shared__ float red[8];
#pragma unroll
    for (int m = 16; m >= 1; m >>= 1) lsum += __shfl_xor_sync(0xffffffffu, lsum, m);
    int lane = threadIdx.x & 31, warp = threadIdx.x >> 5;
    if (lane == 0) red[warp] = lsum;
    __syncthreads();
    if (warp == 0) {
        float v = (lane < 8) ? red[lane] : 0.0f;
#pragma unroll
        for (int m = 4; m >= 1; m >>= 1) v += __shfl_xor_sync(0xffffffffu, v, m);
        if (lane == 0) atomicAdd(out_loss, v * (1.0f / 8388608.0f));
    }
}

// ---------------- launch ----------------
extern "C" void kernel_launch(void* const* d_in, const int* in_sizes, int n_in,
                              void* d_out, int out_size) {
    const float* x       = (const float*)d_in[0];
    const float* cb      = (const float*)d_in[1];
    const float* ema_cs  = (const float*)d_in[2];
    const float* ema_sum = (const float*)d_in[3];

    float* out      = (float*)d_out;
    float* out_q    = out;
    float* out_loss = out + 8388608;
    float* out_cb   = out_loss + 1;
    float* out_cs   = out_cb + 65536;
    float* out_sum  = out_cs + 1024;

    const int FB_SMEM = 2 * DDIM * FB_PITCH * 4;   // 67584
    static bool attr_set = false;
    if (!attr_set) {
        cudaFuncSetAttribute(k_main, cudaFuncAttributeMaxDynamicSharedMemorySize, SM_MAIN_TOT);
        cudaFuncSetAttribute(k_fallback, cudaFuncAttributeMaxDynamicSharedMemorySize, FB_SMEM);
        attr_set = true;
    }

    k_zero<<<64, 1024>>>(out_loss);
    k_split<<<4, 256>>>(cb);
    k_main<<<NROWS / BM2, 512, SM_MAIN_TOT>>>(x);
    k_fallback<<<296, 256, FB_SMEM>>>(x, cb);
    k_scatter<<<2048, 256>>>(x);
    k_stats<<<1, 1024>>>(ema_cs, out_cs);
    k_upd<<<64, 1024>>>(ema_sum, out_sum, out_cb);
    k_quant<<<4096, 256>>>(x, out_q, out_loss);
}